// round 7
// baseline (speedup 1.0000x reference)
#include <cuda_runtime.h>
#include <cstdint>
#include <cstddef>

// Problem constants (match reference_code)
#define Cc 5
#define Hh 4096
#define Ww 4096
#define Nn 2000
#define PHh 64
#define PWw 64

// Fire-and-forget vector reduction: 4 consecutive f32, 16B-aligned address.
__device__ __forceinline__ void red_add_v4(float* addr, float x0, float x1,
                                           float x2, float x3) {
    asm volatile("red.global.add.v4.f32 [%0], {%1, %2, %3, %4};"
                 :: "l"(addr), "f"(x0), "f"(x1), "f"(x2), "f"(x3)
                 : "memory");
}

__device__ __forceinline__ void red_add(float* addr, float v) {
    asm volatile("red.global.add.f32 [%0], %1;"
                 :: "l"(addr), "f"(v)
                 : "memory");
}

// One block per (source n, band c) plane: blockIdx.x = n*C + c, which is
// exactly the patch-plane index into patches[N][C][PH][PW].
// Each 64-float patch row is scattered as: scalar head (align to 16B in the
// frame), 15-16 red.v4.f32, scalar tail. Work items per plane: PH rows x 16
// slots; slot s < nvec is a v4, slot s == nvec (only when misaligned) handles
// the head+tail scalars for that row.
__global__ __launch_bounds__(256)
void splat_kernel(const float* __restrict__ patches,
                  const int*   __restrict__ positions,
                  float*       __restrict__ out) {
    const int blk = blockIdx.x;
    const int n = blk / Cc;
    const int c = blk - n * Cc;

    const int ph0 = __ldg(&positions[2 * n]);
    const int pw0 = __ldg(&positions[2 * n + 1]);

    const int a    = pw0 & 3;
    const int head = (4 - a) & 3;          // scalar elems at row start
    const int nvec = (PWw - head) >> 2;    // 16 if aligned, else 15
    const int vend = head + (nvec << 2);   // start of scalar tail

    const float* __restrict__ p =
        patches + (size_t)blk * (PHh * PWw);
    float* __restrict__ ob =
        out + (size_t)c * ((size_t)Hh * Ww) + (size_t)ph0 * Ww + pw0;

    #pragma unroll 4
    for (int item = threadIdx.x; item < PHh * 16; item += 256) {
        const int row = item >> 4;
        const int s   = item & 15;
        float*       orow = ob + (size_t)row * Ww;
        const float* prow = p + row * PWw;

        if (s < nvec) {
            const int col = head + (s << 2);
            float x0, x1, x2, x3;
            if (head == 0) {
                // patch row base is 16B-aligned and col % 4 == 0
                const float4 v = *reinterpret_cast<const float4*>(prow + col);
                x0 = v.x; x1 = v.y; x2 = v.z; x3 = v.w;
            } else {
                x0 = prow[col];     x1 = prow[col + 1];
                x2 = prow[col + 2]; x3 = prow[col + 3];
            }
            red_add_v4(orow + col, x0, x1, x2, x3);
        } else {
            // s == nvec == 15 only when misaligned: head + tail scalars
            #pragma unroll
            for (int col = 0; col < 3; ++col) {
                if (col < head) red_add(orow + col, prow[col]);
            }
            #pragma unroll
            for (int k = 0; k < 3; ++k) {
                const int col = vend + k;
                if (col < PWw) red_add(orow + col, prow[col]);
            }
        }
    }
}

extern "C" void kernel_launch(void* const* d_in, const int* in_sizes, int n_in,
                              void* d_out, int out_size) {
    // Inputs per metadata order: patches (N*C*PH*PW f32), positions (N*2 i32).
    // Defensive: identify by element count in case ordering differs.
    const float* patches;
    const int*   positions;
    if (in_sizes[0] == Nn * 2) {
        positions = (const int*)d_in[0];
        patches   = (const float*)d_in[1];
    } else {
        patches   = (const float*)d_in[0];
        positions = (const int*)d_in[1];
    }
    float* out = (float*)d_out;

    // Zero the scene buffer (d_out is poisoned before timing). Memset node is
    // graph-capturable.
    cudaMemsetAsync(out, 0, (size_t)out_size * sizeof(float), 0);

    // One block per (n, c) patch plane.
    splat_kernel<<<Nn * Cc, 256, 0, 0>>>(patches, positions, out);
}